// round 1
// baseline (speedup 1.0000x reference)
#include <cuda_runtime.h>
#include <cuda_bf16.h>
#include <math.h>

// Problem constants (B=1, DIM=512, T=8, H=64, W=64)
#define MDIM 512          // output channels (M)
#define KDIM 512          // input channels (K)
#define NDIM 32768        // spatial tokens t*h*w (N)
#define SQRT_C 22.62741699796952f

// ---------------- scratch (no allocations allowed) ----------------
__device__ float g_Wf[MDIM * KDIM];   // fused weight  W_proj @ (W_v * gamma)
__device__ float g_bias[MDIM];        // fused bias    W_proj @ b_v + b_proj
__device__ float g_s[NDIM];           // per-token scale sqrt(512)/||x[:,n]||

// ---------------- kernel 1: fuse weights  Wf[o][c] = sum_k wp[o][k]*Wv[k][c]*gamma[c]
// grid: 128 blocks (4 output rows each), 512 threads (one per c)
__global__ __launch_bounds__(512) void fuse_weights_kernel(
    const float* __restrict__ w_proj,   // [512,512] row-major (o,k)
    const float* __restrict__ w_qkv,    // [1536,512] row-major; V rows at 1024
    const float* __restrict__ gamma,    // [512]
    float* __restrict__ Wf)             // [512,512]
{
    __shared__ float wp[4][KDIM];
    const int o0  = blockIdx.x * 4;
    const int tid = threadIdx.x;

    #pragma unroll
    for (int i = 0; i < 4; i++)
        wp[i][tid] = w_proj[(o0 + i) * KDIM + tid];
    __syncthreads();

    const float* __restrict__ Bv = w_qkv + 1024 * KDIM;   // W_v [k][c]
    float a0 = 0.f, a1 = 0.f, a2 = 0.f, a3 = 0.f;
    #pragma unroll 4
    for (int k = 0; k < KDIM; k++) {
        float b = Bv[k * KDIM + tid];
        a0 = fmaf(wp[0][k], b, a0);
        a1 = fmaf(wp[1][k], b, a1);
        a2 = fmaf(wp[2][k], b, a2);
        a3 = fmaf(wp[3][k], b, a3);
    }
    const float g = gamma[tid];
    Wf[(o0 + 0) * KDIM + tid] = a0 * g;
    Wf[(o0 + 1) * KDIM + tid] = a1 * g;
    Wf[(o0 + 2) * KDIM + tid] = a2 * g;
    Wf[(o0 + 3) * KDIM + tid] = a3 * g;
}

// ---------------- kernel 2: fused bias ----------------
__global__ __launch_bounds__(512) void fuse_bias_kernel(
    const float* __restrict__ w_proj,
    const float* __restrict__ b_qkv,    // [1536]; V part at 1024
    const float* __restrict__ b_proj,
    float* __restrict__ bias)
{
    const int o = threadIdx.x;
    float acc = b_proj[o];
    #pragma unroll 8
    for (int k = 0; k < KDIM; k++)
        acc = fmaf(w_proj[o * KDIM + k], b_qkv[1024 + k], acc);
    bias[o] = acc;
}

// ---------------- kernel 3: per-token RMS scale ----------------
// 128 blocks x 256 threads; thread n accumulates over c with stride N (coalesced)
__global__ __launch_bounds__(256) void scale_kernel(
    const float* __restrict__ x, float* __restrict__ s)
{
    const int n = blockIdx.x * blockDim.x + threadIdx.x;
    float acc = 0.f;
    #pragma unroll 8
    for (int c = 0; c < KDIM; c++) {
        float v = x[c * NDIM + n];
        acc = fmaf(v, v, acc);
    }
    s[n] = SQRT_C / fmaxf(sqrtf(acc), 1e-12f);
}

// ---------------- kernel 4: main GEMM + epilogue ----------------
// C[m][n] = (sum_k Wf[m][k] * x[k][n]) * s[n] + bias[m] + x[m][n]
#define BM 128
#define BN 128
#define BK 16
#define TM 8
#define TN 8

__global__ __launch_bounds__(256) void main_gemm_kernel(
    const float* __restrict__ A,     // Wf [M,K] row-major
    const float* __restrict__ B,     // x  [K,N] row-major (channel-major input)
    const float* __restrict__ s,     // [N]
    const float* __restrict__ bias,  // [M]
    float* __restrict__ C)           // out [M,N]
{
    __shared__ float As[BK][BM];
    __shared__ float Bs[BK][BN];

    const int tid = threadIdx.x;
    const int tx  = tid & 15;          // n direction
    const int ty  = tid >> 4;          // m direction
    const int m0  = blockIdx.y * BM;
    const int n0  = blockIdx.x * BN;

    // A tile loader: 128x16, float4 along k; thread -> rows tid/4 and tid/4+64
    const int a_row = tid >> 2;
    const int a_vec = (tid & 3) * 4;
    // B tile loader: 16x128; thread -> row tid/16, cols (tid%16)*4 and +64
    const int b_row = tid >> 4;
    const int b_col = (tid & 15) * 4;

    const float* Aptr = A + (size_t)m0 * KDIM;
    const float* Bptr = B + n0;

    float acc[TM][TN] = {};

    for (int k0 = 0; k0 < KDIM; k0 += BK) {
        #pragma unroll
        for (int r = 0; r < 2; r++) {
            const int row = a_row + r * 64;
            float4 v = *reinterpret_cast<const float4*>(Aptr + row * KDIM + k0 + a_vec);
            As[a_vec + 0][row] = v.x;
            As[a_vec + 1][row] = v.y;
            As[a_vec + 2][row] = v.z;
            As[a_vec + 3][row] = v.w;
        }
        #pragma unroll
        for (int r = 0; r < 2; r++) {
            const int col = b_col + r * 64;
            *reinterpret_cast<float4*>(&Bs[b_row][col]) =
                *reinterpret_cast<const float4*>(Bptr + (size_t)(k0 + b_row) * NDIM + col);
        }
        __syncthreads();

        #pragma unroll
        for (int kk = 0; kk < BK; kk++) {
            float ra[TM], rb[TN];
            #pragma unroll
            for (int i = 0; i < TM; i++) ra[i] = As[kk][ty * TM + i];
            #pragma unroll
            for (int j = 0; j < TN; j++) rb[j] = Bs[kk][tx * TN + j];
            #pragma unroll
            for (int i = 0; i < TM; i++)
                #pragma unroll
                for (int j = 0; j < TN; j++)
                    acc[i][j] = fmaf(ra[i], rb[j], acc[i][j]);
        }
        __syncthreads();
    }

    // Epilogue: scale by s[n], add fused bias and residual x[m][n]
    #pragma unroll
    for (int i = 0; i < TM; i++) {
        const int m  = m0 + ty * TM + i;
        const float bm = bias[m];
        const float* xrow = B + (size_t)m * NDIM;   // identity uses same [c][n] layout
        float* crow = C + (size_t)m * NDIM;
        #pragma unroll
        for (int j = 0; j < TN; j += 4) {
            const int n = n0 + tx * TN + j;
            float4 sv = *reinterpret_cast<const float4*>(s + n);
            float4 xv = *reinterpret_cast<const float4*>(xrow + n);
            float4 ov;
            ov.x = fmaf(acc[i][j + 0], sv.x, bm + xv.x);
            ov.y = fmaf(acc[i][j + 1], sv.y, bm + xv.y);
            ov.z = fmaf(acc[i][j + 2], sv.z, bm + xv.z);
            ov.w = fmaf(acc[i][j + 3], sv.w, bm + xv.w);
            *reinterpret_cast<float4*>(crow + n) = ov;
        }
    }
}

// ---------------- launcher ----------------
extern "C" void kernel_launch(void* const* d_in, const int* in_sizes, int n_in,
                              void* d_out, int out_size)
{
    const float* x      = (const float*)d_in[0];   // [1,512,8,64,64]
    const float* gamma  = (const float*)d_in[1];   // [512]
    const float* w_qkv  = (const float*)d_in[2];   // [1536,512]
    const float* b_qkv  = (const float*)d_in[3];   // [1536]
    const float* w_proj = (const float*)d_in[4];   // [512,512]
    const float* b_proj = (const float*)d_in[5];   // [512]
    float* out = (float*)d_out;

    float *Wf, *bias, *s;
    cudaGetSymbolAddress((void**)&Wf,   g_Wf);
    cudaGetSymbolAddress((void**)&bias, g_bias);
    cudaGetSymbolAddress((void**)&s,    g_s);

    fuse_weights_kernel<<<MDIM / 4, 512>>>(w_proj, w_qkv, gamma, Wf);
    fuse_bias_kernel<<<1, 512>>>(w_proj, b_qkv, b_proj, bias);
    scale_kernel<<<NDIM / 256, 256>>>(x, s);

    dim3 grid(NDIM / BN, MDIM / BM);   // 256 x 4 = 1024 CTAs
    main_gemm_kernel<<<grid, 256>>>(Wf, x, s, bias, out);
}

// round 3
// speedup vs baseline: 1.8494x; 1.8494x over previous
#include <cuda_runtime.h>
#include <cuda_bf16.h>
#include <cstdint>
#include <math.h>

// Problem constants (B=1, DIM=512, T=8, H=64, W=64)
#define MDIM 512
#define KDIM 512
#define NDIM 32768
#define SQRT_C 22.62741699796952f

// GEMM tiling
#define BM 128
#define BN 128
#define BK 32
#define NITER (KDIM / BK)      // 16
#define ROWF 36                // padded row length in floats (144 bytes)
#define ROWB 144
#define A_STAGE_B (BM * ROWB)  // 18432
#define B_STAGE_B (BN * ROWB)  // 18432
#define SMEM_TOTAL (2 * A_STAGE_B + 2 * B_STAGE_B)   // 73728

// ---------------- scratch ----------------
__device__ float g_Wf[MDIM * KDIM];
__device__ float g_bias[MDIM];

// ---------------- helpers ----------------
__device__ __forceinline__ uint32_t smem_u32(const void* p) {
    uint32_t a;
    asm("{ .reg .u64 t; cvta.to.shared.u64 t, %1; cvt.u32.u64 %0, t; }" : "=r"(a) : "l"(p));
    return a;
}
__device__ __forceinline__ void cp_async16(uint32_t dst, const void* src) {
    asm volatile("cp.async.cg.shared.global [%0], [%1], 16;" :: "r"(dst), "l"(src) : "memory");
}
__device__ __forceinline__ float to_tf32(float v) {
    float o;
    asm("cvt.rna.tf32.f32 %0, %1;" : "=f"(o) : "f"(v));
    return o;
}
__device__ __forceinline__ void mma_tf32(float c[4], uint32_t a0, uint32_t a1, uint32_t a2, uint32_t a3,
                                         uint32_t b0, uint32_t b1) {
    asm volatile(
        "mma.sync.aligned.m16n8k8.row.col.f32.tf32.tf32.f32 "
        "{%0,%1,%2,%3}, {%4,%5,%6,%7}, {%8,%9}, {%0,%1,%2,%3};"
        : "+f"(c[0]), "+f"(c[1]), "+f"(c[2]), "+f"(c[3])
        : "r"(a0), "r"(a1), "r"(a2), "r"(a3), "r"(b0), "r"(b1));
}

// ---------------- kernel 1: fuse weights (pre-rounded to tf32) ----------------
__global__ __launch_bounds__(512) void fuse_weights_kernel(
    const float* __restrict__ w_proj, const float* __restrict__ w_qkv,
    const float* __restrict__ gamma, float* __restrict__ Wf)
{
    __shared__ float wp[8][KDIM];
    const int o0 = blockIdx.x * 8;
    const int tid = threadIdx.x;
    #pragma unroll
    for (int i = 0; i < 8; i++)
        wp[i][tid] = w_proj[(o0 + i) * KDIM + tid];
    __syncthreads();

    const float* __restrict__ Bv = w_qkv + 1024 * KDIM;
    float a[8] = {};
    #pragma unroll 4
    for (int k = 0; k < KDIM; k++) {
        float b = Bv[k * KDIM + tid];
        #pragma unroll
        for (int i = 0; i < 8; i++) a[i] = fmaf(wp[i][k], b, a[i]);
    }
    const float g = gamma[tid];
    #pragma unroll
    for (int i = 0; i < 8; i++)
        Wf[(o0 + i) * KDIM + tid] = to_tf32(a[i] * g);
}

// ---------------- kernel 2: fused bias ----------------
__global__ __launch_bounds__(512) void fuse_bias_kernel(
    const float* __restrict__ w_proj, const float* __restrict__ b_qkv,
    const float* __restrict__ b_proj, float* __restrict__ bias)
{
    const int o = threadIdx.x;
    float acc = b_proj[o];
    #pragma unroll 8
    for (int k = 0; k < KDIM; k++)
        acc = fmaf(w_proj[o * KDIM + k], b_qkv[1024 + k], acc);
    bias[o] = acc;
}

// ---------------- kernel 3: mma.sync tf32 GEMM + fused RMS scale + epilogue ----------------
// D[m][n] = sum_k Wf[m][k]*x[k][n]; out = D*s[n] + bias[m] + x[m][n]
// s[n] computed in-kernel from the B tiles as they stream through.
__global__ __launch_bounds__(256, 2) void main_gemm_kernel(
    const float* __restrict__ A,     // Wf [512,512] row-major
    const float* __restrict__ Bx,    // x  [512,32768] row-major
    const float* __restrict__ bias,
    float* __restrict__ C)
{
    extern __shared__ char smem[];
    const uint32_t sbase = smem_u32(smem);
    const int tid  = threadIdx.x;
    const int lane = tid & 31;
    const int wid  = tid >> 5;
    const int wm   = wid >> 2;          // 0..1
    const int wn   = wid & 3;           // 0..3
    const int ty   = lane >> 2;         // 0..7
    const int tx   = lane & 3;          // 0..3
    const int m0   = blockIdx.y * BM;
    const int n0   = blockIdx.x * BN;

    // A loader (cp.async): tid -> (row = tid>>3 (+32r), kv = tid&7)
    const int a_row = tid >> 3;
    const int a_kv  = tid & 7;
    const uint32_t a_dst0 = sbase + (uint32_t)(a_row * ROWB + a_kv * 16);
    const float* a_src0 = A + (size_t)(m0 + a_row) * KDIM + a_kv * 4;

    // B loader: tid -> n = tid&127, kq2 = tid>>7 (0/1). 16 k-values per chunk.
    const int b_n   = tid & 127;
    const int b_kq2 = tid >> 7;
    const float* b_src0 = Bx + (size_t)(4 * b_kq2) * NDIM + n0 + b_n;
    const uint32_t b_dst0 = sbase + 2 * A_STAGE_B + (uint32_t)(b_n * ROWB + b_kq2 * 16);

    float bv[16];
    float ssq = 0.f;
    float c[4][4][4] = {};

    // ---- prologue: stage 0 ----
    {
        #pragma unroll
        for (int r = 0; r < 4; r++)
            cp_async16(a_dst0 + r * 32 * ROWB, a_src0 + (size_t)(r * 32) * KDIM);
        asm volatile("cp.async.commit_group;" ::: "memory");
        #pragma unroll
        for (int g = 0; g < 4; g++)
            #pragma unroll
            for (int j = 0; j < 4; j++) {
                float v = b_src0[(size_t)(8 * g + j) * NDIM];
                bv[g * 4 + j] = v;
                ssq = fmaf(v, v, ssq);
            }
    }

    int p = 0;
    for (int it = 0; it < NITER; ++it) {
        asm volatile("cp.async.wait_group 0;" ::: "memory");
        __syncthreads();

        // store B regs (tf32-rounded) into stage p
        {
            const uint32_t bd = b_dst0 + (uint32_t)p * B_STAGE_B;
            #pragma unroll
            for (int g = 0; g < 4; g++) {
                float4 v;
                v.x = to_tf32(bv[g * 4 + 0]);
                v.y = to_tf32(bv[g * 4 + 1]);
                v.z = to_tf32(bv[g * 4 + 2]);
                v.w = to_tf32(bv[g * 4 + 3]);
                asm volatile("st.shared.v4.f32 [%0], {%1,%2,%3,%4};"
                             :: "r"(bd + g * 32), "f"(v.x), "f"(v.y), "f"(v.z), "f"(v.w) : "memory");
            }
        }
        __syncthreads();

        // prefetch next stage
        if (it + 1 < NITER) {
            const int k0n = (it + 1) * BK;
            const uint32_t ad = a_dst0 + (uint32_t)(p ^ 1) * A_STAGE_B;
            const float* as = a_src0 + k0n;
            #pragma unroll
            for (int r = 0; r < 4; r++)
                cp_async16(ad + r * 32 * ROWB, as + (size_t)(r * 32) * KDIM);
            asm volatile("cp.async.commit_group;" ::: "memory");
            const float* bs = b_src0 + (size_t)k0n * NDIM;
            #pragma unroll
            for (int g = 0; g < 4; g++)
                #pragma unroll
                for (int j = 0; j < 4; j++) {
                    float v = bs[(size_t)(8 * g + j) * NDIM];
                    bv[g * 4 + j] = v;
                    ssq = fmaf(v, v, ssq);
                }
        }

        // ---- compute stage p ----
        {
            const float* As = (const float*)(smem + (size_t)p * A_STAGE_B);
            const float* Bs = (const float*)(smem + 2 * A_STAGE_B + (size_t)p * B_STAGE_B);
            #pragma unroll
            for (int kk = 0; kk < 4; kk++) {
                const int k = kk * 8;
                uint32_t a[4][4];
                #pragma unroll
                for (int mt = 0; mt < 4; mt++) {
                    const float* ap = As + (wm * 64 + mt * 16 + ty) * ROWF + k + tx;
                    a[mt][0] = __float_as_uint(ap[0]);
                    a[mt][1] = __float_as_uint(ap[8 * ROWF]);
                    a[mt][2] = __float_as_uint(ap[4]);
                    a[mt][3] = __float_as_uint(ap[8 * ROWF + 4]);
                }
                uint32_t b[4][2];
                #pragma unroll
                for (int nt = 0; nt < 4; nt++) {
                    const float* bp = Bs + (wn * 32 + nt * 8 + ty) * ROWF + k + tx;
                    b[nt][0] = __float_as_uint(bp[0]);
                    b[nt][1] = __float_as_uint(bp[4]);
                }
                #pragma unroll
                for (int mt = 0; mt < 4; mt++)
                    #pragma unroll
                    for (int nt = 0; nt < 4; nt++)
                        mma_tf32(c[mt][nt], a[mt][0], a[mt][1], a[mt][2], a[mt][3],
                                 b[nt][0], b[nt][1]);
            }
        }
        p ^= 1;
    }

    // ---- RMS scale reduction (reuse smem) ----
    __syncthreads();
    float* red  = (float*)smem;        // [0, 256)
    float* s_sm = (float*)smem + 512;  // [512, 640)
    red[tid] = ssq;
    __syncthreads();
    if (tid < 128) {
        float t = red[tid] + red[tid + 128];
        s_sm[tid] = SQRT_C / fmaxf(sqrtf(t), 1e-12f);
    }
    __syncthreads();

    // ---- epilogue ----
    #pragma unroll
    for (int mt = 0; mt < 4; mt++) {
        #pragma unroll
        for (int h = 0; h < 2; h++) {
            const int m = m0 + wm * 64 + mt * 16 + ty + h * 8;
            const float bm = bias[m];
            const float* xrow = Bx + (size_t)m * NDIM + n0;
            float*       crow = C + (size_t)m * NDIM + n0;
            #pragma unroll
            for (int nt = 0; nt < 4; nt++) {
                const int nc = wn * 32 + nt * 8 + 2 * tx;
                float2 xv = *reinterpret_cast<const float2*>(xrow + nc);
                float s0 = s_sm[nc], s1 = s_sm[nc + 1];
                float2 ov;
                ov.x = fmaf(c[mt][nt][h * 2 + 0], s0, bm + xv.x);
                ov.y = fmaf(c[mt][nt][h * 2 + 1], s1, bm + xv.y);
                *reinterpret_cast<float2*>(crow + nc) = ov;
            }
        }
    }
}

// ---------------- launcher ----------------
extern "C" void kernel_launch(void* const* d_in, const int* in_sizes, int n_in,
                              void* d_out, int out_size)
{
    const float* x      = (const float*)d_in[0];
    const float* gamma  = (const float*)d_in[1];
    const float* w_qkv  = (const float*)d_in[2];
    const float* b_qkv  = (const float*)d_in[3];
    const float* w_proj = (const float*)d_in[4];
    const float* b_proj = (const float*)d_in[5];
    float* out = (float*)d_out;

    float *Wf, *bias;
    cudaGetSymbolAddress((void**)&Wf,   g_Wf);
    cudaGetSymbolAddress((void**)&bias, g_bias);

    cudaFuncSetAttribute(main_gemm_kernel,
                         cudaFuncAttributeMaxDynamicSharedMemorySize, SMEM_TOTAL);

    fuse_weights_kernel<<<MDIM / 8, 512>>>(w_proj, w_qkv, gamma, Wf);
    fuse_bias_kernel<<<1, 512>>>(w_proj, b_qkv, b_proj, bias);

    dim3 grid(NDIM / BN, MDIM / BM);   // 256 x 4 = 1024 CTAs
    main_gemm_kernel<<<grid, 256, SMEM_TOTAL>>>(Wf, x, bias, out);
}

// round 4
// speedup vs baseline: 3.4946x; 1.8896x over previous
#include <cuda_runtime.h>
#include <cuda_bf16.h>
#include <cstdint>
#include <math.h>

// Problem constants (B=1, DIM=512, T=8, H=64, W=64)
#define MDIM 512
#define KDIM 512
#define NDIM 32768
#define SQRT_C 22.62741699796952f

// GEMM tiling
#define BM 128
#define BN 128
#define BK 32
#define NITER (KDIM / BK)      // 16
#define STAGES 3
#define ROWF 36                // A padded row length in floats
#define ROWB 144               // A padded row bytes
#define BROWF 136              // B padded row length in floats ((8*tx+ty)%32 conflict-free)
#define BROWB 544
#define A_STAGE_B (BM * ROWB)          // 18432
#define B_STAGE_B (BK * BROWB)         // 17408
#define STAGE_B   (A_STAGE_B + B_STAGE_B)   // 35840
#define SMEM_TOTAL (STAGES * STAGE_B)       // 107520

// ---------------- scratch ----------------
__device__ float g_Wf[MDIM * KDIM];
__device__ float g_bias[MDIM];
__device__ float g_s[NDIM];

// ---------------- helpers ----------------
__device__ __forceinline__ uint32_t smem_u32(const void* p) {
    uint32_t a;
    asm("{ .reg .u64 t; cvta.to.shared.u64 t, %1; cvt.u32.u64 %0, t; }" : "=r"(a) : "l"(p));
    return a;
}
__device__ __forceinline__ void cp_async16(uint32_t dst, const void* src) {
    asm volatile("cp.async.cg.shared.global [%0], [%1], 16;" :: "r"(dst), "l"(src) : "memory");
}
__device__ __forceinline__ float to_tf32(float v) {
    float o;
    asm("cvt.rna.tf32.f32 %0, %1;" : "=f"(o) : "f"(v));
    return o;
}
__device__ __forceinline__ void mma_tf32(float c[4], uint32_t a0, uint32_t a1, uint32_t a2, uint32_t a3,
                                         uint32_t b0, uint32_t b1) {
    asm volatile(
        "mma.sync.aligned.m16n8k8.row.col.f32.tf32.tf32.f32 "
        "{%0,%1,%2,%3}, {%4,%5,%6,%7}, {%8,%9}, {%0,%1,%2,%3};"
        : "+f"(c[0]), "+f"(c[1]), "+f"(c[2]), "+f"(c[3])
        : "r"(a0), "r"(a1), "r"(a2), "r"(a3), "r"(b0), "r"(b1));
}

// ---------------- kernel 1: fuse weights ----------------
// Wf[o][c] = tf32( (sum_k wp[o0+o][k] * Wv[k][c]) * gamma[c] )
// grid (32 o-blocks, 4 c-blocks), 256 threads = 128 c-lanes x 2 k-halves.
#define WPT_STRIDE 20   // padded row (floats) for transposed wp tile; 16B-aligned rows
__global__ __launch_bounds__(256) void fuse_weights_kernel(
    const float* __restrict__ w_proj, const float* __restrict__ w_qkv,
    const float* __restrict__ gamma, float* __restrict__ Wf)
{
    __shared__ float wpT[KDIM * WPT_STRIDE];   // wpT[k][o], 40KB; reused as red buffer
    const int tid = threadIdx.x;
    const int o0  = blockIdx.x * 16;
    const int c0  = blockIdx.y * 128;

    // stage w_proj rows [o0..o0+16) transposed: wpT[k][o]
    {
        const float4* src = reinterpret_cast<const float4*>(w_proj + (size_t)o0 * KDIM);
        #pragma unroll
        for (int j = 0; j < 8; j++) {
            const int v  = j * 256 + tid;      // 2048 float4s
            const int o  = v >> 7;             // 0..15
            const int k4 = (v & 127) * 4;
            float4 w = src[v];
            wpT[(k4 + 0) * WPT_STRIDE + o] = w.x;
            wpT[(k4 + 1) * WPT_STRIDE + o] = w.y;
            wpT[(k4 + 2) * WPT_STRIDE + o] = w.z;
            wpT[(k4 + 3) * WPT_STRIDE + o] = w.w;
        }
    }
    __syncthreads();

    const int cl = tid & 127;
    const int kh = tid >> 7;                   // k-half: 0 or 1
    const int c  = c0 + cl;
    const float* __restrict__ Bv = w_qkv + (size_t)1024 * KDIM;
    const float* bp = Bv + (size_t)(kh * 256) * KDIM + c;
    const float* wrow = wpT + (kh * 256) * WPT_STRIDE;

    float acc[16] = {};
    #pragma unroll 4
    for (int i = 0; i < 256; i++) {
        float b = bp[(size_t)i * KDIM];
        const float4* w4 = reinterpret_cast<const float4*>(wrow + i * WPT_STRIDE);
        #pragma unroll
        for (int q = 0; q < 4; q++) {
            float4 w = w4[q];
            acc[q * 4 + 0] = fmaf(w.x, b, acc[q * 4 + 0]);
            acc[q * 4 + 1] = fmaf(w.y, b, acc[q * 4 + 1]);
            acc[q * 4 + 2] = fmaf(w.z, b, acc[q * 4 + 2]);
            acc[q * 4 + 3] = fmaf(w.w, b, acc[q * 4 + 3]);
        }
    }

    __syncthreads();                 // done reading wpT; reuse as reduction buffer
    float* red = wpT;                // [16][128]
    if (kh == 1) {
        #pragma unroll
        for (int o = 0; o < 16; o++) red[o * 128 + cl] = acc[o];
    }
    __syncthreads();
    if (kh == 0) {
        const float g = gamma[c];
        #pragma unroll
        for (int o = 0; o < 16; o++) {
            float v = (acc[o] + red[o * 128 + cl]) * g;
            Wf[(size_t)(o0 + o) * KDIM + c] = to_tf32(v);
        }
    }
}

// ---------------- kernel 2: fused bias (warp per output row) ----------------
__global__ __launch_bounds__(256) void fuse_bias_kernel(
    const float* __restrict__ w_proj, const float* __restrict__ b_qkv,
    const float* __restrict__ b_proj, float* __restrict__ bias)
{
    const int lane = threadIdx.x & 31;
    const int o    = blockIdx.x * 8 + (threadIdx.x >> 5);
    const float* wp = w_proj + (size_t)o * KDIM;
    const float* bq = b_qkv + 1024;
    float acc = 0.f;
    #pragma unroll
    for (int i = 0; i < 16; i++) {
        const int k = lane + 32 * i;
        acc = fmaf(wp[k], bq[k], acc);
    }
    #pragma unroll
    for (int off = 16; off > 0; off >>= 1)
        acc += __shfl_xor_sync(0xFFFFFFFFu, acc, off);
    if (lane == 0) bias[o] = acc + b_proj[o];
}

// ---------------- kernel 3: per-token RMS scale (4-way K split) ----------------
__global__ __launch_bounds__(256) void scale_kernel(
    const float* __restrict__ x, float* __restrict__ s)
{
    __shared__ float red[256];
    const int tid = threadIdx.x;
    const int n_l = tid & 63;
    const int q   = tid >> 6;
    const int n   = blockIdx.x * 64 + n_l;

    const float* p = x + (size_t)(q * 128) * NDIM + n;
    float acc = 0.f;
    #pragma unroll 16
    for (int c = 0; c < 128; c++) {
        float v = p[(size_t)c * NDIM];
        acc = fmaf(v, v, acc);
    }
    red[tid] = acc;
    __syncthreads();
    if (tid < 64) {
        float t = red[tid] + red[tid + 64] + red[tid + 128] + red[tid + 192];
        s[n] = SQRT_C / fmaxf(sqrtf(t), 1e-12f);
    }
}

// ---------------- kernel 4: mma.sync tf32 GEMM, 3-stage cp.async pipeline ----------------
__global__ __launch_bounds__(256, 2) void main_gemm_kernel(
    const float* __restrict__ A,     // Wf [512,512] row-major (tf32-rounded)
    const float* __restrict__ Bx,    // x  [512,32768] row-major
    const float* __restrict__ s,     // [32768]
    const float* __restrict__ bias,  // [512]
    float* __restrict__ C)
{
    extern __shared__ char smem[];
    const uint32_t sbase = smem_u32(smem);
    const int tid  = threadIdx.x;
    const int lane = tid & 31;
    const int wid  = tid >> 5;
    const int wm   = wid >> 2;          // 0..1
    const int wn   = wid & 3;           // 0..3
    const int ty   = lane >> 2;         // 0..7
    const int tx   = lane & 3;          // 0..3
    const int m0   = blockIdx.y * BM;
    const int n0   = blockIdx.x * BN;

    // loader mappings (per chunk: 1024 x 16B for A, 1024 x 16B for B; 4+4 per thread)
    const int a_row = tid >> 3;         // 0..31 (rows +32r)
    const int a_seg = tid & 7;          // 16B segment within 128B k-row
    const int b_row = tid >> 3;         // 0..31 (k within chunk)
    const int b_seg = tid & 7;          // segments b_seg + 8j

    const float* a_src = A + (size_t)(m0 + a_row) * KDIM + a_seg * 4;
    const float* b_src = Bx + (size_t)b_row * NDIM + n0 + b_seg * 4;

    float c[4][4][4] = {};

    // issue chunk 'ck' into stage 'st'
    auto issue = [&](int ck, int st) {
        const uint32_t ab = sbase + st * STAGE_B;
        const uint32_t bb = ab + A_STAGE_B;
        const int k0 = ck * BK;
        #pragma unroll
        for (int r = 0; r < 4; r++)
            cp_async16(ab + (uint32_t)((a_row + 32 * r) * ROWB + a_seg * 16),
                       a_src + k0 + (size_t)(32 * r) * KDIM);
        #pragma unroll
        for (int j = 0; j < 4; j++)
            cp_async16(bb + (uint32_t)(b_row * BROWB + (b_seg + 8 * j) * 16),
                       b_src + (size_t)k0 * NDIM + 32 * j);
        asm volatile("cp.async.commit_group;" ::: "memory");
    };

    // prologue: 2 chunks in flight
    issue(0, 0);
    issue(1, 1);

    int st = 0;       // stage being computed
    int st2 = 2;      // stage to fill next
    #pragma unroll 1
    for (int it = 0; it < NITER; ++it) {
        if (it + 2 < NITER) {
            issue(it + 2, st2);
            if (++st2 == STAGES) st2 = 0;
            asm volatile("cp.async.wait_group 2;" ::: "memory");
        } else if (it + 1 < NITER) {
            asm volatile("cp.async.wait_group 1;" ::: "memory");
        } else {
            asm volatile("cp.async.wait_group 0;" ::: "memory");
        }
        __syncthreads();

        {
            const float* As = (const float*)(smem + (size_t)st * STAGE_B);
            const float* Bs = (const float*)(smem + (size_t)st * STAGE_B + A_STAGE_B);
            #pragma unroll
            for (int kk = 0; kk < 4; kk++) {
                const int k = kk * 8;
                uint32_t a[4][4];
                #pragma unroll
                for (int mt = 0; mt < 4; mt++) {
                    const float* ap = As + (wm * 64 + mt * 16 + ty) * ROWF + k + tx;
                    a[mt][0] = __float_as_uint(ap[0]);
                    a[mt][1] = __float_as_uint(ap[8 * ROWF]);
                    a[mt][2] = __float_as_uint(ap[4]);
                    a[mt][3] = __float_as_uint(ap[8 * ROWF + 4]);
                }
                uint32_t b[4][2];
                #pragma unroll
                for (int nt = 0; nt < 4; nt++) {
                    const float* bp = Bs + (k + tx) * BROWF + wn * 32 + nt * 8 + ty;
                    b[nt][0] = __float_as_uint(bp[0]);
                    b[nt][1] = __float_as_uint(bp[4 * BROWF]);
                }
                #pragma unroll
                for (int mt = 0; mt < 4; mt++)
                    #pragma unroll
                    for (int nt = 0; nt < 4; nt++)
                        mma_tf32(c[mt][nt], a[mt][0], a[mt][1], a[mt][2], a[mt][3],
                                 b[nt][0], b[nt][1]);
            }
        }
        __syncthreads();
        if (++st == STAGES) st = 0;
    }

    // ---- epilogue: out = D*s[n] + bias[m] + x[m][n] ----
    #pragma unroll
    for (int mt = 0; mt < 4; mt++) {
        #pragma unroll
        for (int h = 0; h < 2; h++) {
            const int m = m0 + wm * 64 + mt * 16 + ty + h * 8;
            const float bm = bias[m];
            const float* xrow = Bx + (size_t)m * NDIM + n0;
            float*       crow = C + (size_t)m * NDIM + n0;
            #pragma unroll
            for (int nt = 0; nt < 4; nt++) {
                const int nc = wn * 32 + nt * 8 + 2 * tx;
                float2 xv = *reinterpret_cast<const float2*>(xrow + nc);
                float2 sv = *reinterpret_cast<const float2*>(s + n0 + nc);
                float2 ov;
                ov.x = fmaf(c[mt][nt][h * 2 + 0], sv.x, bm + xv.x);
                ov.y = fmaf(c[mt][nt][h * 2 + 1], sv.y, bm + xv.y);
                *reinterpret_cast<float2*>(crow + nc) = ov;
            }
        }
    }
}

// ---------------- launcher ----------------
extern "C" void kernel_launch(void* const* d_in, const int* in_sizes, int n_in,
                              void* d_out, int out_size)
{
    const float* x      = (const float*)d_in[0];
    const float* gamma  = (const float*)d_in[1];
    const float* w_qkv  = (const float*)d_in[2];
    const float* b_qkv  = (const float*)d_in[3];
    const float* w_proj = (const float*)d_in[4];
    const float* b_proj = (const float*)d_in[5];
    float* out = (float*)d_out;

    float *Wf, *bias, *s;
    cudaGetSymbolAddress((void**)&Wf,   g_Wf);
    cudaGetSymbolAddress((void**)&bias, g_bias);
    cudaGetSymbolAddress((void**)&s,    g_s);

    cudaFuncSetAttribute(main_gemm_kernel,
                         cudaFuncAttributeMaxDynamicSharedMemorySize, SMEM_TOTAL);

    dim3 fwgrid(MDIM / 16, 4);
    fuse_weights_kernel<<<fwgrid, 256>>>(w_proj, w_qkv, gamma, Wf);
    fuse_bias_kernel<<<MDIM / 8, 256>>>(w_proj, b_qkv, b_proj, bias);
    scale_kernel<<<NDIM / 64, 256>>>(x, s);

    dim3 grid(NDIM / BN, MDIM / BM);   // 256 x 4 = 1024 CTAs
    main_gemm_kernel<<<grid, 256, SMEM_TOTAL>>>(Wf, x, s, bias, out);
}

// round 5
// speedup vs baseline: 4.2739x; 1.2230x over previous
#include <cuda_runtime.h>
#include <cuda_fp16.h>
#include <cstdint>
#include <math.h>

// Problem constants (B=1, DIM=512, T=8, H=64, W=64)
#define MDIM 512
#define KDIM 512
#define NDIM 32768
#define SQRT_C 22.62741699796952f

// GEMM tiling
#define BM 128
#define BN 128
#define BK 32
#define NITER (KDIM / BK)      // 16
#define STAGES 4
#define AROW_H 40              // A padded row (halves) -> 80B, ldmatrix conflict-free
#define BROW_H 136             // B padded row (halves) -> 272B, ldmatrix conflict-free
#define A_BYTES (BM * AROW_H * 2)      // 10240
#define B_BYTES (BK * BROW_H * 2)      // 8704
#define STAGE_B (A_BYTES + B_BYTES)    // 18944
#define SMEM_TOTAL (STAGES * STAGE_B)  // 75776

// ---------------- scratch ----------------
__device__ __half g_Wf[MDIM * KDIM];      // fused weight, fp16
__device__ __half g_xh[KDIM * NDIM];      // x converted to fp16
__device__ float  g_bias[MDIM];
__device__ float  g_s[NDIM];

// ---------------- helpers ----------------
__device__ __forceinline__ uint32_t smem_u32(const void* p) {
    uint32_t a;
    asm("{ .reg .u64 t; cvta.to.shared.u64 t, %1; cvt.u32.u64 %0, t; }" : "=r"(a) : "l"(p));
    return a;
}
__device__ __forceinline__ void cp_async16(uint32_t dst, const void* src) {
    asm volatile("cp.async.cg.shared.global [%0], [%1], 16;" :: "r"(dst), "l"(src) : "memory");
}
#define LDSM_X4(r0, r1, r2, r3, addr)                                         \
    asm volatile("ldmatrix.sync.aligned.m8n8.x4.shared.b16 {%0,%1,%2,%3}, [%4];" \
        : "=r"(r0), "=r"(r1), "=r"(r2), "=r"(r3) : "r"(addr))
#define LDSM_X4_T(r0, r1, r2, r3, addr)                                       \
    asm volatile("ldmatrix.sync.aligned.m8n8.x4.trans.shared.b16 {%0,%1,%2,%3}, [%4];" \
        : "=r"(r0), "=r"(r1), "=r"(r2), "=r"(r3) : "r"(addr))

__device__ __forceinline__ void mma_f16(float c[4], uint32_t a0, uint32_t a1, uint32_t a2, uint32_t a3,
                                        uint32_t b0, uint32_t b1) {
    asm volatile(
        "mma.sync.aligned.m16n8k16.row.col.f32.f16.f16.f32 "
        "{%0,%1,%2,%3}, {%4,%5,%6,%7}, {%8,%9}, {%0,%1,%2,%3};"
        : "+f"(c[0]), "+f"(c[1]), "+f"(c[2]), "+f"(c[3])
        : "r"(a0), "r"(a1), "r"(a2), "r"(a3), "r"(b0), "r"(b1));
}

// ---------------- kernel 1: fuse weights -> fp16 ----------------
// Wf[o][c] = half( (sum_k wp[o0+o][k] * Wv[k][c]) * gamma[c] )
#define WPT_STRIDE 20
__global__ __launch_bounds__(256) void fuse_weights_kernel(
    const float* __restrict__ w_proj, const float* __restrict__ w_qkv,
    const float* __restrict__ gamma, __half* __restrict__ Wf)
{
    __shared__ float wpT[KDIM * WPT_STRIDE];
    const int tid = threadIdx.x;
    const int o0  = blockIdx.x * 16;
    const int c0  = blockIdx.y * 128;

    {
        const float4* src = reinterpret_cast<const float4*>(w_proj + (size_t)o0 * KDIM);
        #pragma unroll
        for (int j = 0; j < 8; j++) {
            const int v  = j * 256 + tid;
            const int o  = v >> 7;
            const int k4 = (v & 127) * 4;
            float4 w = src[v];
            wpT[(k4 + 0) * WPT_STRIDE + o] = w.x;
            wpT[(k4 + 1) * WPT_STRIDE + o] = w.y;
            wpT[(k4 + 2) * WPT_STRIDE + o] = w.z;
            wpT[(k4 + 3) * WPT_STRIDE + o] = w.w;
        }
    }
    __syncthreads();

    const int cl = tid & 127;
    const int kh = tid >> 7;
    const int c  = c0 + cl;
    const float* __restrict__ Bv = w_qkv + (size_t)1024 * KDIM;
    const float* bp = Bv + (size_t)(kh * 256) * KDIM + c;
    const float* wrow = wpT + (kh * 256) * WPT_STRIDE;

    float acc[16] = {};
    #pragma unroll 4
    for (int i = 0; i < 256; i++) {
        float b = bp[(size_t)i * KDIM];
        const float4* w4 = reinterpret_cast<const float4*>(wrow + i * WPT_STRIDE);
        #pragma unroll
        for (int q = 0; q < 4; q++) {
            float4 w = w4[q];
            acc[q * 4 + 0] = fmaf(w.x, b, acc[q * 4 + 0]);
            acc[q * 4 + 1] = fmaf(w.y, b, acc[q * 4 + 1]);
            acc[q * 4 + 2] = fmaf(w.z, b, acc[q * 4 + 2]);
            acc[q * 4 + 3] = fmaf(w.w, b, acc[q * 4 + 3]);
        }
    }

    __syncthreads();
    float* red = wpT;
    if (kh == 1) {
        #pragma unroll
        for (int o = 0; o < 16; o++) red[o * 128 + cl] = acc[o];
    }
    __syncthreads();
    if (kh == 0) {
        const float g = gamma[c];
        #pragma unroll
        for (int o = 0; o < 16; o++)
            Wf[(size_t)(o0 + o) * KDIM + c] = __float2half_rn((acc[o] + red[o * 128 + cl]) * g);
    }
}

// ---------------- kernel 2: fused bias ----------------
__global__ __launch_bounds__(256) void fuse_bias_kernel(
    const float* __restrict__ w_proj, const float* __restrict__ b_qkv,
    const float* __restrict__ b_proj, float* __restrict__ bias)
{
    const int lane = threadIdx.x & 31;
    const int o    = blockIdx.x * 8 + (threadIdx.x >> 5);
    const float* wp = w_proj + (size_t)o * KDIM;
    const float* bq = b_qkv + 1024;
    float acc = 0.f;
    #pragma unroll
    for (int i = 0; i < 16; i++) {
        const int k = lane + 32 * i;
        acc = fmaf(wp[k], bq[k], acc);
    }
    #pragma unroll
    for (int off = 16; off > 0; off >>= 1)
        acc += __shfl_xor_sync(0xFFFFFFFFu, acc, off);
    if (lane == 0) bias[o] = acc + b_proj[o];
}

// ---------------- kernel 3: RMS scale + fp16 conversion ----------------
__global__ __launch_bounds__(256) void scale_kernel(
    const float* __restrict__ x, float* __restrict__ s, __half* __restrict__ xh)
{
    __shared__ float red[256];
    const int tid = threadIdx.x;
    const int n_l = tid & 63;
    const int q   = tid >> 6;
    const int n   = blockIdx.x * 64 + n_l;

    const float* p = x + (size_t)(q * 128) * NDIM + n;
    __half* ph = xh + (size_t)(q * 128) * NDIM + n;
    float acc = 0.f;
    #pragma unroll 8
    for (int c = 0; c < 128; c++) {
        float v = p[(size_t)c * NDIM];
        acc = fmaf(v, v, acc);
        ph[(size_t)c * NDIM] = __float2half_rn(v);
    }
    red[tid] = acc;
    __syncthreads();
    if (tid < 64) {
        float t = red[tid] + red[tid + 64] + red[tid + 128] + red[tid + 192];
        s[n] = SQRT_C / fmaxf(sqrtf(t), 1e-12f);
    }
}

// ---------------- kernel 4: fp16 mma GEMM, 4-stage cp.async, ldmatrix ----------------
__global__ __launch_bounds__(256, 2) void main_gemm_kernel(
    const __half* __restrict__ A,    // Wf [512,512] fp16
    const __half* __restrict__ Bh,   // x_h [512,32768] fp16
    const float* __restrict__ Bx,    // x fp32 (residual)
    const float* __restrict__ s,
    const float* __restrict__ bias,
    float* __restrict__ C)
{
    extern __shared__ char smem[];
    const uint32_t sbase = smem_u32(smem);
    const int tid  = threadIdx.x;
    const int lane = tid & 31;
    const int wid  = tid >> 5;
    const int wm   = wid >> 2;          // 0..1
    const int wn   = wid & 3;           // 0..3
    const int ty   = lane >> 2;
    const int tx   = lane & 3;
    const int m0   = blockIdx.y * BM;
    const int n0   = blockIdx.x * BN;

    // loaders: A 128 rows x 64B (4 segs); B 32 rows x 256B (16 segs); 4 cp.async/thread
    const int a_row = tid >> 1;          // 0..127
    const int a_sp  = (tid & 1) * 2;     // seg pair base
    const int b_row = tid >> 3;          // 0..31
    const int b_sp  = (tid & 7) * 2;

    const __half* a_src = A + (size_t)(m0 + a_row) * KDIM + a_sp * 8;
    const __half* b_src = Bh + (size_t)b_row * NDIM + n0 + b_sp * 8;

    float c[4][4][4] = {};

    auto issue = [&](int ck) {
        const int st = ck & 3;
        const uint32_t ab = sbase + st * STAGE_B;
        const uint32_t bb = ab + A_BYTES;
        const int k0 = ck * BK;
        #pragma unroll
        for (int ss = 0; ss < 2; ss++)
            cp_async16(ab + (uint32_t)(a_row * 80 + (a_sp + ss) * 16),
                       a_src + k0 + ss * 8);
        #pragma unroll
        for (int ss = 0; ss < 2; ss++)
            cp_async16(bb + (uint32_t)(b_row * 272 + (b_sp + ss) * 16),
                       b_src + (size_t)k0 * NDIM + ss * 8);
        asm volatile("cp.async.commit_group;" ::: "memory");
    };

    issue(0); issue(1); issue(2);

    // ldmatrix base addresses (bytes)
    const uint32_t a_lm = (uint32_t)(((wm * 64 + (lane & 15)) * AROW_H + (lane >> 4) * 8) * 2);
    const uint32_t b_lm = (uint32_t)((A_BYTES) + (((lane & 15)) * BROW_H + wn * 32 + (lane >> 4) * 8) * 2);

    #pragma unroll 1
    for (int it = 0; it < NITER; ++it) {
        if (it + 3 < NITER) {
            issue(it + 3);
            asm volatile("cp.async.wait_group 3;" ::: "memory");
        } else if (it + 2 < NITER) {
            asm volatile("cp.async.wait_group 2;" ::: "memory");
        } else if (it + 1 < NITER) {
            asm volatile("cp.async.wait_group 1;" ::: "memory");
        } else {
            asm volatile("cp.async.wait_group 0;" ::: "memory");
        }
        __syncthreads();

        const uint32_t stb = sbase + (uint32_t)(it & 3) * STAGE_B;
        #pragma unroll
        for (int kk = 0; kk < 2; kk++) {
            uint32_t a[4][4];
            #pragma unroll
            for (int mt = 0; mt < 4; mt++)
                LDSM_X4(a[mt][0], a[mt][1], a[mt][2], a[mt][3],
                        stb + a_lm + mt * (16 * AROW_H * 2) + kk * 32);
            uint32_t b[4][2];
            #pragma unroll
            for (int ntp = 0; ntp < 2; ntp++)
                LDSM_X4_T(b[ntp * 2][0], b[ntp * 2][1], b[ntp * 2 + 1][0], b[ntp * 2 + 1][1],
                          stb + b_lm + kk * (16 * BROW_H * 2) + ntp * 32);
            #pragma unroll
            for (int mt = 0; mt < 4; mt++)
                #pragma unroll
                for (int nt = 0; nt < 4; nt++)
                    mma_f16(c[mt][nt], a[mt][0], a[mt][1], a[mt][2], a[mt][3],
                            b[nt][0], b[nt][1]);
        }
        __syncthreads();
    }

    // ---- epilogue: out = D*s[n] + bias[m] + x[m][n] ----
    #pragma unroll
    for (int mt = 0; mt < 4; mt++) {
        #pragma unroll
        for (int h = 0; h < 2; h++) {
            const int m = m0 + wm * 64 + mt * 16 + ty + h * 8;
            const float bm = bias[m];
            const float* xrow = Bx + (size_t)m * NDIM + n0;
            float*       crow = C + (size_t)m * NDIM + n0;
            #pragma unroll
            for (int nt = 0; nt < 4; nt++) {
                const int nc = wn * 32 + nt * 8 + 2 * tx;
                float2 xv = *reinterpret_cast<const float2*>(xrow + nc);
                float2 sv = *reinterpret_cast<const float2*>(s + n0 + nc);
                float2 ov;
                ov.x = fmaf(c[mt][nt][h * 2 + 0], sv.x, bm + xv.x);
                ov.y = fmaf(c[mt][nt][h * 2 + 1], sv.y, bm + xv.y);
                *reinterpret_cast<float2*>(crow + nc) = ov;
            }
        }
    }
}

// ---------------- launcher ----------------
extern "C" void kernel_launch(void* const* d_in, const int* in_sizes, int n_in,
                              void* d_out, int out_size)
{
    const float* x      = (const float*)d_in[0];
    const float* gamma  = (const float*)d_in[1];
    const float* w_qkv  = (const float*)d_in[2];
    const float* b_qkv  = (const float*)d_in[3];
    const float* w_proj = (const float*)d_in[4];
    const float* b_proj = (const float*)d_in[5];
    float* out = (float*)d_out;

    __half *Wf, *xh;
    float *bias, *s;
    cudaGetSymbolAddress((void**)&Wf,   g_Wf);
    cudaGetSymbolAddress((void**)&xh,   g_xh);
    cudaGetSymbolAddress((void**)&bias, g_bias);
    cudaGetSymbolAddress((void**)&s,    g_s);

    cudaFuncSetAttribute(main_gemm_kernel,
                         cudaFuncAttributeMaxDynamicSharedMemorySize, SMEM_TOTAL);

    dim3 fwgrid(MDIM / 16, 4);
    fuse_weights_kernel<<<fwgrid, 256>>>(w_proj, w_qkv, gamma, Wf);
    fuse_bias_kernel<<<MDIM / 8, 256>>>(w_proj, b_qkv, b_proj, bias);
    scale_kernel<<<NDIM / 64, 256>>>(x, s, xh);

    dim3 grid(NDIM / BN, MDIM / BM);   // 256 x 4 = 1024 CTAs
    main_gemm_kernel<<<grid, 256, SMEM_TOTAL>>>(Wf, xh, x, s, bias, out);
}

// round 6
// speedup vs baseline: 5.3484x; 1.2514x over previous
#include <cuda_runtime.h>
#include <cuda_fp16.h>
#include <cstdint>
#include <math.h>

// Problem constants (B=1, DIM=512, T=8, H=64, W=64)
#define MDIM 512
#define KDIM 512
#define NDIM 32768
#define SQRT_C 22.62741699796952f

// GEMM tiling (shared by main gemm and fuse-weights gemm)
#define BM 128
#define BN 128
#define BK 32
#define NITER (KDIM / BK)      // 16
#define STAGES 4
#define AROW_H 40              // A padded row (halves) -> 80B
#define BROW_H 136             // B padded row (halves) -> 272B
#define A_BYTES (BM * AROW_H * 2)      // 10240
#define B_BYTES (BK * BROW_H * 2)      // 8704
#define STAGE_B (A_BYTES + B_BYTES)    // 18944
#define SMEM_TOTAL (STAGES * STAGE_B)  // 75776

// ---------------- scratch ----------------
__device__ __half g_Wf[MDIM * KDIM];      // fused weight, fp16
__device__ __half g_xh[KDIM * NDIM];      // x converted to fp16
__device__ __half g_wph[MDIM * KDIM];     // w_proj fp16
__device__ __half g_wvh[MDIM * KDIM];     // (W_v * gamma) fp16
__device__ float  g_bias[MDIM];
__device__ float  g_s[NDIM];

// ---------------- helpers ----------------
__device__ __forceinline__ uint32_t smem_u32(const void* p) {
    uint32_t a;
    asm("{ .reg .u64 t; cvta.to.shared.u64 t, %1; cvt.u32.u64 %0, t; }" : "=r"(a) : "l"(p));
    return a;
}
__device__ __forceinline__ void cp_async16(uint32_t dst, const void* src) {
    asm volatile("cp.async.cg.shared.global [%0], [%1], 16;" :: "r"(dst), "l"(src) : "memory");
}
#define LDSM_X4(r0, r1, r2, r3, addr)                                         \
    asm volatile("ldmatrix.sync.aligned.m8n8.x4.shared.b16 {%0,%1,%2,%3}, [%4];" \
        : "=r"(r0), "=r"(r1), "=r"(r2), "=r"(r3) : "r"(addr))
#define LDSM_X4_T(r0, r1, r2, r3, addr)                                       \
    asm volatile("ldmatrix.sync.aligned.m8n8.x4.trans.shared.b16 {%0,%1,%2,%3}, [%4];" \
        : "=r"(r0), "=r"(r1), "=r"(r2), "=r"(r3) : "r"(addr))

__device__ __forceinline__ void mma_f16(float c[4], uint32_t a0, uint32_t a1, uint32_t a2, uint32_t a3,
                                        uint32_t b0, uint32_t b1) {
    asm volatile(
        "mma.sync.aligned.m16n8k16.row.col.f32.f16.f16.f32 "
        "{%0,%1,%2,%3}, {%4,%5,%6,%7}, {%8,%9}, {%0,%1,%2,%3};"
        : "+f"(c[0]), "+f"(c[1]), "+f"(c[2]), "+f"(c[3])
        : "r"(a0), "r"(a1), "r"(a2), "r"(a3), "r"(b0), "r"(b1));
}

// ---------------- convert kernels ----------------
__global__ __launch_bounds__(256) void f2h_kernel(
    const float* __restrict__ in, __half* __restrict__ out)
{
    const int i = (blockIdx.x * 256 + threadIdx.x) * 4;
    float4 v = *reinterpret_cast<const float4*>(in + i);
    *reinterpret_cast<__half2*>(out + i)     = __floats2half2_rn(v.x, v.y);
    *reinterpret_cast<__half2*>(out + i + 2) = __floats2half2_rn(v.z, v.w);
}

// out[k][c] = half(in[k][c] * gamma[c]), rows of 512
__global__ __launch_bounds__(256) void f2h_gamma_kernel(
    const float* __restrict__ in, const float* __restrict__ gamma,
    __half* __restrict__ out)
{
    const int i = (blockIdx.x * 256 + threadIdx.x) * 4;
    const int c = i & (KDIM - 1);
    float4 g = *reinterpret_cast<const float4*>(gamma + c);
    float4 v = *reinterpret_cast<const float4*>(in + i);
    *reinterpret_cast<__half2*>(out + i)     = __floats2half2_rn(v.x * g.x, v.y * g.y);
    *reinterpret_cast<__half2*>(out + i + 2) = __floats2half2_rn(v.z * g.z, v.w * g.w);
}

// ---------------- fused bias ----------------
__global__ __launch_bounds__(256) void fuse_bias_kernel(
    const float* __restrict__ w_proj, const float* __restrict__ b_qkv,
    const float* __restrict__ b_proj, float* __restrict__ bias)
{
    const int lane = threadIdx.x & 31;
    const int o    = blockIdx.x * 8 + (threadIdx.x >> 5);
    const float* wp = w_proj + (size_t)o * KDIM;
    const float* bq = b_qkv + 1024;
    float acc = 0.f;
    #pragma unroll
    for (int i = 0; i < 16; i++) {
        const int k = lane + 32 * i;
        acc = fmaf(wp[k], bq[k], acc);
    }
    #pragma unroll
    for (int off = 16; off > 0; off >>= 1)
        acc += __shfl_xor_sync(0xFFFFFFFFu, acc, off);
    if (lane == 0) bias[o] = acc + b_proj[o];
}

// ---------------- RMS scale + fp16 conversion (2 tokens/thread) ----------------
__global__ __launch_bounds__(256) void scale_kernel(
    const float* __restrict__ x, float* __restrict__ s, __half* __restrict__ xh)
{
    __shared__ float2 red[256];
    const int tid = threadIdx.x;
    const int nl  = tid & 63;
    const int q   = tid >> 6;
    const int n   = blockIdx.x * 128 + nl * 2;

    const float2* p = reinterpret_cast<const float2*>(x + (size_t)(q * 128) * NDIM + n);
    __half2* ph = reinterpret_cast<__half2*>(xh + (size_t)(q * 128) * NDIM + n);
    float ax = 0.f, ay = 0.f;
    #pragma unroll 8
    for (int c = 0; c < 128; c++) {
        float2 v = p[(size_t)c * (NDIM / 2)];
        ax = fmaf(v.x, v.x, ax);
        ay = fmaf(v.y, v.y, ay);
        ph[(size_t)c * (NDIM / 2)] = __floats2half2_rn(v.x, v.y);
    }
    red[tid] = make_float2(ax, ay);
    __syncthreads();
    if (tid < 64) {
        float2 a = red[tid], b = red[tid + 64], c2 = red[tid + 128], d = red[tid + 192];
        float tx2 = a.x + b.x + c2.x + d.x;
        float ty2 = a.y + b.y + c2.y + d.y;
        float2 sv;
        sv.x = SQRT_C / fmaxf(sqrtf(tx2), 1e-12f);
        sv.y = SQRT_C / fmaxf(sqrtf(ty2), 1e-12f);
        *reinterpret_cast<float2*>(s + blockIdx.x * 128 + tid * 2) = sv;
    }
}

// ---------------- fuse-weights GEMM: Wf = w_proj(fp16) @ (Wv*gamma)(fp16) ----------------
// grid (4 n-blocks, 4 m-blocks); identical pipeline to main gemm, B stride 512.
__global__ __launch_bounds__(256, 2) void fuse_weights_mma(
    const __half* __restrict__ A,    // w_projh [512,512]
    const __half* __restrict__ Bh,   // wvh [512,512]
    __half* __restrict__ Wf)
{
    extern __shared__ char smem[];
    const uint32_t sbase = smem_u32(smem);
    const int tid  = threadIdx.x;
    const int lane = tid & 31;
    const int wid  = tid >> 5;
    const int wm   = wid >> 2;
    const int wn   = wid & 3;
    const int ty   = lane >> 2;
    const int tx   = lane & 3;
    const int m0   = blockIdx.y * BM;
    const int n0   = blockIdx.x * BN;

    const int a_row = tid >> 1;
    const int a_sp  = (tid & 1) * 2;
    const int b_row = tid >> 3;
    const int b_sp  = (tid & 7) * 2;
    const __half* a_src = A + (size_t)(m0 + a_row) * KDIM + a_sp * 8;
    const __half* b_src = Bh + (size_t)b_row * 512 + n0 + b_sp * 8;

    float c[4][4][4] = {};

    auto issue = [&](int ck) {
        const int st = ck & 3;
        const uint32_t ab = sbase + st * STAGE_B;
        const uint32_t bb = ab + A_BYTES;
        const int k0 = ck * BK;
        #pragma unroll
        for (int ss = 0; ss < 2; ss++)
            cp_async16(ab + (uint32_t)(a_row * 80 + (a_sp + ss) * 16), a_src + k0 + ss * 8);
        #pragma unroll
        for (int ss = 0; ss < 2; ss++)
            cp_async16(bb + (uint32_t)(b_row * 272 + (b_sp + ss) * 16),
                       b_src + (size_t)k0 * 512 + ss * 8);
        asm volatile("cp.async.commit_group;" ::: "memory");
    };

    issue(0); issue(1); issue(2);

    const uint32_t a_lm = (uint32_t)(((wm * 64 + (lane & 15)) * AROW_H + (lane >> 4) * 8) * 2);
    const uint32_t b_lm = (uint32_t)(A_BYTES + (((lane & 15)) * BROW_H + wn * 32 + (lane >> 4) * 8) * 2);

    #pragma unroll 1
    for (int it = 0; it < NITER; ++it) {
        if (it + 3 < NITER)      asm volatile("cp.async.wait_group 2;" ::: "memory");
        else if (it + 2 < NITER) asm volatile("cp.async.wait_group 1;" ::: "memory");
        else                     asm volatile("cp.async.wait_group 0;" ::: "memory");
        __syncthreads();
        if (it + 3 < NITER) issue(it + 3);

        const uint32_t stb = sbase + (uint32_t)(it & 3) * STAGE_B;
        #pragma unroll
        for (int kk = 0; kk < 2; kk++) {
            uint32_t a[4][4];
            #pragma unroll
            for (int mt = 0; mt < 4; mt++)
                LDSM_X4(a[mt][0], a[mt][1], a[mt][2], a[mt][3],
                        stb + a_lm + mt * (16 * AROW_H * 2) + kk * 32);
            uint32_t b[4][2];
            #pragma unroll
            for (int ntp = 0; ntp < 2; ntp++)
                LDSM_X4_T(b[ntp * 2][0], b[ntp * 2][1], b[ntp * 2 + 1][0], b[ntp * 2 + 1][1],
                          stb + b_lm + kk * (16 * BROW_H * 2) + ntp * 32);
            #pragma unroll
            for (int mt = 0; mt < 4; mt++)
                #pragma unroll
                for (int nt = 0; nt < 4; nt++)
                    mma_f16(c[mt][nt], a[mt][0], a[mt][1], a[mt][2], a[mt][3],
                            b[nt][0], b[nt][1]);
        }
    }

    #pragma unroll
    for (int mt = 0; mt < 4; mt++)
        #pragma unroll
        for (int h = 0; h < 2; h++) {
            const int m = m0 + wm * 64 + mt * 16 + ty + h * 8;
            #pragma unroll
            for (int nt = 0; nt < 4; nt++) {
                const int nc = wn * 32 + nt * 8 + 2 * tx;
                *reinterpret_cast<__half2*>(Wf + (size_t)m * KDIM + n0 + nc) =
                    __floats2half2_rn(c[mt][nt][h * 2 + 0], c[mt][nt][h * 2 + 1]);
            }
        }
}

// ---------------- main GEMM: single-barrier 4-stage pipeline ----------------
__global__ __launch_bounds__(256, 2) void main_gemm_kernel(
    const __half* __restrict__ A,    // Wf [512,512] fp16
    const __half* __restrict__ Bh,   // x_h [512,32768] fp16
    const float* __restrict__ Bx,    // x fp32 (residual)
    const float* __restrict__ s,
    const float* __restrict__ bias,
    float* __restrict__ C)
{
    extern __shared__ char smem[];
    const uint32_t sbase = smem_u32(smem);
    const int tid  = threadIdx.x;
    const int lane = tid & 31;
    const int wid  = tid >> 5;
    const int wm   = wid >> 2;
    const int wn   = wid & 3;
    const int ty   = lane >> 2;
    const int tx   = lane & 3;
    const int m0   = blockIdx.y * BM;
    const int n0   = blockIdx.x * BN;

    const int a_row = tid >> 1;
    const int a_sp  = (tid & 1) * 2;
    const int b_row = tid >> 3;
    const int b_sp  = (tid & 7) * 2;
    const __half* a_src = A + (size_t)(m0 + a_row) * KDIM + a_sp * 8;
    const __half* b_src = Bh + (size_t)b_row * NDIM + n0 + b_sp * 8;

    float c[4][4][4] = {};

    auto issue = [&](int ck) {
        const int st = ck & 3;
        const uint32_t ab = sbase + st * STAGE_B;
        const uint32_t bb = ab + A_BYTES;
        const int k0 = ck * BK;
        #pragma unroll
        for (int ss = 0; ss < 2; ss++)
            cp_async16(ab + (uint32_t)(a_row * 80 + (a_sp + ss) * 16), a_src + k0 + ss * 8);
        #pragma unroll
        for (int ss = 0; ss < 2; ss++)
            cp_async16(bb + (uint32_t)(b_row * 272 + (b_sp + ss) * 16),
                       b_src + (size_t)k0 * NDIM + ss * 8);
        asm volatile("cp.async.commit_group;" ::: "memory");
    };

    issue(0); issue(1); issue(2);

    const uint32_t a_lm = (uint32_t)(((wm * 64 + (lane & 15)) * AROW_H + (lane >> 4) * 8) * 2);
    const uint32_t b_lm = (uint32_t)(A_BYTES + (((lane & 15)) * BROW_H + wn * 32 + (lane >> 4) * 8) * 2);

    #pragma unroll 1
    for (int it = 0; it < NITER; ++it) {
        if (it + 3 < NITER)      asm volatile("cp.async.wait_group 2;" ::: "memory");
        else if (it + 2 < NITER) asm volatile("cp.async.wait_group 1;" ::: "memory");
        else                     asm volatile("cp.async.wait_group 0;" ::: "memory");
        __syncthreads();
        if (it + 3 < NITER) issue(it + 3);

        const uint32_t stb = sbase + (uint32_t)(it & 3) * STAGE_B;
        #pragma unroll
        for (int kk = 0; kk < 2; kk++) {
            uint32_t a[4][4];
            #pragma unroll
            for (int mt = 0; mt < 4; mt++)
                LDSM_X4(a[mt][0], a[mt][1], a[mt][2], a[mt][3],
                        stb + a_lm + mt * (16 * AROW_H * 2) + kk * 32);
            uint32_t b[4][2];
            #pragma unroll
            for (int ntp = 0; ntp < 2; ntp++)
                LDSM_X4_T(b[ntp * 2][0], b[ntp * 2][1], b[ntp * 2 + 1][0], b[ntp * 2 + 1][1],
                          stb + b_lm + kk * (16 * BROW_H * 2) + ntp * 32);
            #pragma unroll
            for (int mt = 0; mt < 4; mt++)
                #pragma unroll
                for (int nt = 0; nt < 4; nt++)
                    mma_f16(c[mt][nt], a[mt][0], a[mt][1], a[mt][2], a[mt][3],
                            b[nt][0], b[nt][1]);
        }
    }

    // ---- epilogue: out = D*s[n] + bias[m] + x[m][n] ----
    #pragma unroll
    for (int mt = 0; mt < 4; mt++) {
        #pragma unroll
        for (int h = 0; h < 2; h++) {
            const int m = m0 + wm * 64 + mt * 16 + ty + h * 8;
            const float bm = bias[m];
            const float* xrow = Bx + (size_t)m * NDIM + n0;
            float*       crow = C + (size_t)m * NDIM + n0;
            #pragma unroll
            for (int nt = 0; nt < 4; nt++) {
                const int nc = wn * 32 + nt * 8 + 2 * tx;
                float2 xv = *reinterpret_cast<const float2*>(xrow + nc);
                float2 sv = *reinterpret_cast<const float2*>(s + n0 + nc);
                float2 ov;
                ov.x = fmaf(c[mt][nt][h * 2 + 0], sv.x, bm + xv.x);
                ov.y = fmaf(c[mt][nt][h * 2 + 1], sv.y, bm + xv.y);
                *reinterpret_cast<float2*>(crow + nc) = ov;
            }
        }
    }
}

// ---------------- launcher ----------------
extern "C" void kernel_launch(void* const* d_in, const int* in_sizes, int n_in,
                              void* d_out, int out_size)
{
    const float* x      = (const float*)d_in[0];
    const float* gamma  = (const float*)d_in[1];
    const float* w_qkv  = (const float*)d_in[2];
    const float* b_qkv  = (const float*)d_in[3];
    const float* w_proj = (const float*)d_in[4];
    const float* b_proj = (const float*)d_in[5];
    float* out = (float*)d_out;

    __half *Wf, *xh, *wph, *wvh;
    float *bias, *s;
    cudaGetSymbolAddress((void**)&Wf,   g_Wf);
    cudaGetSymbolAddress((void**)&xh,   g_xh);
    cudaGetSymbolAddress((void**)&wph,  g_wph);
    cudaGetSymbolAddress((void**)&wvh,  g_wvh);
    cudaGetSymbolAddress((void**)&bias, g_bias);
    cudaGetSymbolAddress((void**)&s,    g_s);

    cudaFuncSetAttribute(main_gemm_kernel,
                         cudaFuncAttributeMaxDynamicSharedMemorySize, SMEM_TOTAL);
    cudaFuncSetAttribute(fuse_weights_mma,
                         cudaFuncAttributeMaxDynamicSharedMemorySize, SMEM_TOTAL);

    // fp16 conversions (w_proj plain; W_v with gamma folded in)
    f2h_kernel<<<(MDIM * KDIM) / 1024, 256>>>(w_proj, wph);
    f2h_gamma_kernel<<<(MDIM * KDIM) / 1024, 256>>>(w_qkv + (size_t)1024 * KDIM, gamma, wvh);

    dim3 fwgrid(MDIM / BN, MDIM / BM);   // 4 x 4
    fuse_weights_mma<<<fwgrid, 256, SMEM_TOTAL>>>(wph, wvh, Wf);

    fuse_bias_kernel<<<MDIM / 8, 256>>>(w_proj, b_qkv, b_proj, bias);
    scale_kernel<<<NDIM / 128, 256>>>(x, s, xh);

    dim3 grid(NDIM / BN, MDIM / BM);   // 256 x 4 = 1024 CTAs
    main_gemm_kernel<<<grid, 256, SMEM_TOTAL>>>(Wf, xh, x, s, bias, out);
}

// round 7
// speedup vs baseline: 5.8427x; 1.0924x over previous
#include <cuda_runtime.h>
#include <cuda_fp16.h>
#include <cstdint>
#include <math.h>

// Problem constants (B=1, DIM=512, T=8, H=64, W=64)
#define MDIM 512
#define KDIM 512
#define NDIM 32768
#define SQRT_C 22.62741699796952f

// GEMM tiling
#define BM 128
#define BN 128
#define BK 32
#define NITER (KDIM / BK)      // 16
#define STAGES 5
#define AROW_H 40              // A padded row (halves) -> 80B
#define BROW_H 136             // B padded row (halves) -> 272B
#define A_BYTES (BM * AROW_H * 2)      // 10240
#define B_BYTES (BK * BROW_H * 2)      // 8704
#define STAGE_B (A_BYTES + B_BYTES)    // 18944
#define SMEM_TOTAL (STAGES * STAGE_B)  // 94720

// ---------------- scratch ----------------
__device__ __half g_Wf[MDIM * KDIM];      // fused weight, fp16
__device__ __half g_xh[KDIM * NDIM];      // x converted to fp16
__device__ __half g_wph[MDIM * KDIM];     // w_proj fp16
__device__ __half g_wvh[MDIM * KDIM];     // (W_v * gamma) fp16
__device__ float  g_bias[MDIM];
__device__ float  g_s[NDIM];

// ---------------- helpers ----------------
__device__ __forceinline__ uint32_t smem_u32(const void* p) {
    uint32_t a;
    asm("{ .reg .u64 t; cvta.to.shared.u64 t, %1; cvt.u32.u64 %0, t; }" : "=r"(a) : "l"(p));
    return a;
}
__device__ __forceinline__ void cp_async16(uint32_t dst, const void* src) {
    asm volatile("cp.async.cg.shared.global [%0], [%1], 16;" :: "r"(dst), "l"(src) : "memory");
}
#define LDSM_X4(r0, r1, r2, r3, addr)                                         \
    asm volatile("ldmatrix.sync.aligned.m8n8.x4.shared.b16 {%0,%1,%2,%3}, [%4];" \
        : "=r"(r0), "=r"(r1), "=r"(r2), "=r"(r3) : "r"(addr))
#define LDSM_X4_T(r0, r1, r2, r3, addr)                                       \
    asm volatile("ldmatrix.sync.aligned.m8n8.x4.trans.shared.b16 {%0,%1,%2,%3}, [%4];" \
        : "=r"(r0), "=r"(r1), "=r"(r2), "=r"(r3) : "r"(addr))

__device__ __forceinline__ void mma_f16(float c[4], uint32_t a0, uint32_t a1, uint32_t a2, uint32_t a3,
                                        uint32_t b0, uint32_t b1) {
    asm volatile(
        "mma.sync.aligned.m16n8k16.row.col.f32.f16.f16.f32 "
        "{%0,%1,%2,%3}, {%4,%5,%6,%7}, {%8,%9}, {%0,%1,%2,%3};"
        : "+f"(c[0]), "+f"(c[1]), "+f"(c[2]), "+f"(c[3])
        : "r"(a0), "r"(a1), "r"(a2), "r"(a3), "r"(b0), "r"(b1));
}

// ---------------- kernel 1: prep (converts + bias, blockIdx-dispatched) ----------------
__global__ __launch_bounds__(256) void prep_kernel(
    const float* __restrict__ w_proj, const float* __restrict__ w_qkv,
    const float* __restrict__ gamma,  const float* __restrict__ b_qkv,
    const float* __restrict__ b_proj,
    __half* __restrict__ wph, __half* __restrict__ wvh, float* __restrict__ bias)
{
    const int bx  = blockIdx.x;
    const int tid = threadIdx.x;
    if (bx < 256) {
        // f2h: w_proj -> wph
        const int i = (bx * 256 + tid) * 4;
        float4 v = *reinterpret_cast<const float4*>(w_proj + i);
        *reinterpret_cast<__half2*>(wph + i)     = __floats2half2_rn(v.x, v.y);
        *reinterpret_cast<__half2*>(wph + i + 2) = __floats2half2_rn(v.z, v.w);
    } else if (bx < 512) {
        // f2h with gamma: W_v -> wvh
        const float* in = w_qkv + (size_t)1024 * KDIM;
        const int i = ((bx - 256) * 256 + tid) * 4;
        const int c = i & (KDIM - 1);
        float4 g = *reinterpret_cast<const float4*>(gamma + c);
        float4 v = *reinterpret_cast<const float4*>(in + i);
        *reinterpret_cast<__half2*>(wvh + i)     = __floats2half2_rn(v.x * g.x, v.y * g.y);
        *reinterpret_cast<__half2*>(wvh + i + 2) = __floats2half2_rn(v.z * g.z, v.w * g.w);
    } else {
        // bias: warp per output row
        const int lane = tid & 31;
        const int o    = (bx - 512) * 8 + (tid >> 5);
        const float* wp = w_proj + (size_t)o * KDIM;
        const float* bq = b_qkv + 1024;
        float acc = 0.f;
        #pragma unroll
        for (int i = 0; i < 16; i++) {
            const int k = lane + 32 * i;
            acc = fmaf(wp[k], bq[k], acc);
        }
        #pragma unroll
        for (int off = 16; off > 0; off >>= 1)
            acc += __shfl_xor_sync(0xFFFFFFFFu, acc, off);
        if (lane == 0) bias[o] = acc + b_proj[o];
    }
}

// ---------------- kernel 2: scale (blocks 0..255) + fuse-weights mma (blocks 256..271) ----------------
__global__ __launch_bounds__(256, 2) void scale_fw_kernel(
    const float* __restrict__ x, float* __restrict__ s, __half* __restrict__ xh,
    const __half* __restrict__ Awp, const __half* __restrict__ Bwv,
    __half* __restrict__ Wf)
{
    extern __shared__ char smem[];
    const int tid = threadIdx.x;

    if (blockIdx.x < 256) {
        // ---- RMS scale + fp16 conversion, 128 tokens per block ----
        float2* red = reinterpret_cast<float2*>(smem);
        const int nl = tid & 63;
        const int q  = tid >> 6;
        const int n  = blockIdx.x * 128 + nl * 2;

        const float2* p = reinterpret_cast<const float2*>(x + (size_t)(q * 128) * NDIM + n);
        __half2* ph = reinterpret_cast<__half2*>(xh + (size_t)(q * 128) * NDIM + n);
        float ax = 0.f, ay = 0.f;
        #pragma unroll 8
        for (int c = 0; c < 128; c++) {
            float2 v = p[(size_t)c * (NDIM / 2)];
            ax = fmaf(v.x, v.x, ax);
            ay = fmaf(v.y, v.y, ay);
            ph[(size_t)c * (NDIM / 2)] = __floats2half2_rn(v.x, v.y);
        }
        red[tid] = make_float2(ax, ay);
        __syncthreads();
        if (tid < 64) {
            float2 a = red[tid], b = red[tid + 64], c2 = red[tid + 128], d = red[tid + 192];
            float tx2 = a.x + b.x + c2.x + d.x;
            float ty2 = a.y + b.y + c2.y + d.y;
            float2 sv;
            sv.x = SQRT_C / fmaxf(sqrtf(tx2), 1e-12f);
            sv.y = SQRT_C / fmaxf(sqrtf(ty2), 1e-12f);
            *reinterpret_cast<float2*>(s + blockIdx.x * 128 + tid * 2) = sv;
        }
        return;
    }

    // ---- fuse-weights GEMM: Wf = wph @ wvh  (B stride 512) ----
    const uint32_t sbase = smem_u32(smem);
    const int bxx  = blockIdx.x - 256;
    const int lane = tid & 31;
    const int wid  = tid >> 5;
    const int wm   = wid >> 2;
    const int wn   = wid & 3;
    const int ty   = lane >> 2;
    const int tx   = lane & 3;
    const int m0   = (bxx >> 2) * BM;
    const int n0   = (bxx & 3) * BN;

    const int a_row = tid >> 1;
    const int a_sp  = (tid & 1) * 2;
    const int b_row = tid >> 3;
    const int b_sp  = (tid & 7) * 2;
    const __half* a_src = Awp + (size_t)(m0 + a_row) * KDIM + a_sp * 8;
    const __half* b_src = Bwv + (size_t)b_row * 512 + n0 + b_sp * 8;

    float c[4][4][4] = {};

    auto issue = [&](int ck) {
        const uint32_t ab = sbase + (uint32_t)(ck % STAGES) * STAGE_B;
        const uint32_t bb = ab + A_BYTES;
        const int k0 = ck * BK;
        #pragma unroll
        for (int ss = 0; ss < 2; ss++)
            cp_async16(ab + (uint32_t)(a_row * 80 + (a_sp + ss) * 16), a_src + k0 + ss * 8);
        #pragma unroll
        for (int ss = 0; ss < 2; ss++)
            cp_async16(bb + (uint32_t)(b_row * 272 + (b_sp + ss) * 16),
                       b_src + (size_t)k0 * 512 + ss * 8);
        asm volatile("cp.async.commit_group;" ::: "memory");
    };

    issue(0); issue(1); issue(2); issue(3);

    const uint32_t a_lm = (uint32_t)(((wm * 64 + (lane & 15)) * AROW_H + (lane >> 4) * 8) * 2);
    const uint32_t b_lm = (uint32_t)(A_BYTES + (((lane & 15)) * BROW_H + wn * 32 + (lane >> 4) * 8) * 2);

    #pragma unroll 1
    for (int it = 0; it < NITER; ++it) {
        if (it + 3 < NITER)      asm volatile("cp.async.wait_group 3;" ::: "memory");
        else if (it + 2 < NITER) asm volatile("cp.async.wait_group 2;" ::: "memory");
        else if (it + 1 < NITER) asm volatile("cp.async.wait_group 1;" ::: "memory");
        else                     asm volatile("cp.async.wait_group 0;" ::: "memory");
        __syncthreads();
        if (it + 4 < NITER) issue(it + 4);

        const uint32_t stb = sbase + (uint32_t)(it % STAGES) * STAGE_B;
        #pragma unroll
        for (int kk = 0; kk < 2; kk++) {
            uint32_t a[4][4];
            #pragma unroll
            for (int mt = 0; mt < 4; mt++)
                LDSM_X4(a[mt][0], a[mt][1], a[mt][2], a[mt][3],
                        stb + a_lm + mt * (16 * AROW_H * 2) + kk * 32);
            uint32_t b[4][2];
            #pragma unroll
            for (int ntp = 0; ntp < 2; ntp++)
                LDSM_X4_T(b[ntp * 2][0], b[ntp * 2][1], b[ntp * 2 + 1][0], b[ntp * 2 + 1][1],
                          stb + b_lm + kk * (16 * BROW_H * 2) + ntp * 32);
            #pragma unroll
            for (int mt = 0; mt < 4; mt++)
                #pragma unroll
                for (int nt = 0; nt < 4; nt++)
                    mma_f16(c[mt][nt], a[mt][0], a[mt][1], a[mt][2], a[mt][3],
                            b[nt][0], b[nt][1]);
        }
    }

    #pragma unroll
    for (int mt = 0; mt < 4; mt++)
        #pragma unroll
        for (int h = 0; h < 2; h++) {
            const int m = m0 + wm * 64 + mt * 16 + ty + h * 8;
            #pragma unroll
            for (int nt = 0; nt < 4; nt++) {
                const int nc = wn * 32 + nt * 8 + 2 * tx;
                *reinterpret_cast<__half2*>(Wf + (size_t)m * KDIM + n0 + nc) =
                    __floats2half2_rn(c[mt][nt][h * 2 + 0], c[mt][nt][h * 2 + 1]);
            }
        }
}

// ---------------- kernel 3: main GEMM, 5-stage pipeline, fp16 residual ----------------
__global__ __launch_bounds__(256, 2) void main_gemm_kernel(
    const __half* __restrict__ A,    // Wf [512,512] fp16
    const __half* __restrict__ Bh,   // x_h [512,32768] fp16 (operand + residual)
    const float* __restrict__ s,
    const float* __restrict__ bias,
    float* __restrict__ C)
{
    extern __shared__ char smem[];
    const uint32_t sbase = smem_u32(smem);
    const int tid  = threadIdx.x;
    const int lane = tid & 31;
    const int wid  = tid >> 5;
    const int wm   = wid >> 2;
    const int wn   = wid & 3;
    const int ty   = lane >> 2;
    const int tx   = lane & 3;
    const int m0   = blockIdx.y * BM;
    const int n0   = blockIdx.x * BN;

    const int a_row = tid >> 1;
    const int a_sp  = (tid & 1) * 2;
    const int b_row = tid >> 3;
    const int b_sp  = (tid & 7) * 2;
    const __half* a_src = A + (size_t)(m0 + a_row) * KDIM + a_sp * 8;
    const __half* b_src = Bh + (size_t)b_row * NDIM + n0 + b_sp * 8;

    float c[4][4][4] = {};

    auto issue = [&](int ck) {
        const uint32_t ab = sbase + (uint32_t)(ck % STAGES) * STAGE_B;
        const uint32_t bb = ab + A_BYTES;
        const int k0 = ck * BK;
        #pragma unroll
        for (int ss = 0; ss < 2; ss++)
            cp_async16(ab + (uint32_t)(a_row * 80 + (a_sp + ss) * 16), a_src + k0 + ss * 8);
        #pragma unroll
        for (int ss = 0; ss < 2; ss++)
            cp_async16(bb + (uint32_t)(b_row * 272 + (b_sp + ss) * 16),
                       b_src + (size_t)k0 * NDIM + ss * 8);
        asm volatile("cp.async.commit_group;" ::: "memory");
    };

    issue(0); issue(1); issue(2); issue(3);

    const uint32_t a_lm = (uint32_t)(((wm * 64 + (lane & 15)) * AROW_H + (lane >> 4) * 8) * 2);
    const uint32_t b_lm = (uint32_t)(A_BYTES + (((lane & 15)) * BROW_H + wn * 32 + (lane >> 4) * 8) * 2);

    #pragma unroll 1
    for (int it = 0; it < NITER; ++it) {
        if (it + 3 < NITER)      asm volatile("cp.async.wait_group 3;" ::: "memory");
        else if (it + 2 < NITER) asm volatile("cp.async.wait_group 2;" ::: "memory");
        else if (it + 1 < NITER) asm volatile("cp.async.wait_group 1;" ::: "memory");
        else                     asm volatile("cp.async.wait_group 0;" ::: "memory");
        __syncthreads();
        if (it + 4 < NITER) issue(it + 4);

        const uint32_t stb = sbase + (uint32_t)(it % STAGES) * STAGE_B;
        #pragma unroll
        for (int kk = 0; kk < 2; kk++) {
            uint32_t a[4][4];
            #pragma unroll
            for (int mt = 0; mt < 4; mt++)
                LDSM_X4(a[mt][0], a[mt][1], a[mt][2], a[mt][3],
                        stb + a_lm + mt * (16 * AROW_H * 2) + kk * 32);
            uint32_t b[4][2];
            #pragma unroll
            for (int ntp = 0; ntp < 2; ntp++)
                LDSM_X4_T(b[ntp * 2][0], b[ntp * 2][1], b[ntp * 2 + 1][0], b[ntp * 2 + 1][1],
                          stb + b_lm + kk * (16 * BROW_H * 2) + ntp * 32);
            #pragma unroll
            for (int mt = 0; mt < 4; mt++)
                #pragma unroll
                for (int nt = 0; nt < 4; nt++)
                    mma_f16(c[mt][nt], a[mt][0], a[mt][1], a[mt][2], a[mt][3],
                            b[nt][0], b[nt][1]);
        }
    }

    // ---- epilogue: out = D*s[n] + bias[m] + xh[m][n] (fp16 residual, L2-hot) ----
    #pragma unroll
    for (int mt = 0; mt < 4; mt++) {
        #pragma unroll
        for (int h = 0; h < 2; h++) {
            const int m = m0 + wm * 64 + mt * 16 + ty + h * 8;
            const float bm = bias[m];
            const __half2* xrow = reinterpret_cast<const __half2*>(Bh + (size_t)m * NDIM + n0);
            float* crow = C + (size_t)m * NDIM + n0;
            #pragma unroll
            for (int nt = 0; nt < 4; nt++) {
                const int nc = wn * 32 + nt * 8 + 2 * tx;
                float2 xv = __half22float2(xrow[nc >> 1]);
                float2 sv = *reinterpret_cast<const float2*>(s + n0 + nc);
                float2 ov;
                ov.x = fmaf(c[mt][nt][h * 2 + 0], sv.x, bm + xv.x);
                ov.y = fmaf(c[mt][nt][h * 2 + 1], sv.y, bm + xv.y);
                *reinterpret_cast<float2*>(crow + nc) = ov;
            }
        }
    }
}

// ---------------- launcher ----------------
extern "C" void kernel_launch(void* const* d_in, const int* in_sizes, int n_in,
                              void* d_out, int out_size)
{
    const float* x      = (const float*)d_in[0];
    const float* gamma  = (const float*)d_in[1];
    const float* w_qkv  = (const float*)d_in[2];
    const float* b_qkv  = (const float*)d_in[3];
    const float* w_proj = (const float*)d_in[4];
    const float* b_proj = (const float*)d_in[5];
    float* out = (float*)d_out;

    __half *Wf, *xh, *wph, *wvh;
    float *bias, *s;
    cudaGetSymbolAddress((void**)&Wf,   g_Wf);
    cudaGetSymbolAddress((void**)&xh,   g_xh);
    cudaGetSymbolAddress((void**)&wph,  g_wph);
    cudaGetSymbolAddress((void**)&wvh,  g_wvh);
    cudaGetSymbolAddress((void**)&bias, g_bias);
    cudaGetSymbolAddress((void**)&s,    g_s);

    cudaFuncSetAttribute(main_gemm_kernel,
                         cudaFuncAttributeMaxDynamicSharedMemorySize, SMEM_TOTAL);
    cudaFuncSetAttribute(scale_fw_kernel,
                         cudaFuncAttributeMaxDynamicSharedMemorySize, SMEM_TOTAL);

    prep_kernel<<<576, 256>>>(w_proj, w_qkv, gamma, b_qkv, b_proj, wph, wvh, bias);
    scale_fw_kernel<<<272, 256, SMEM_TOTAL>>>(x, s, xh, wph, wvh, Wf);

    dim3 grid(NDIM / BN, MDIM / BM);   // 256 x 4 = 1024 CTAs
    main_gemm_kernel<<<grid, 256, SMEM_TOTAL>>>(Wf, xh, s, bias, out);
}